// round 16
// baseline (speedup 1.0000x reference)
#include <cuda_runtime.h>
#include <math.h>
#include <stdint.h>

#define B_   512
#define T_   128
#define N_   500
#define NP_  512
#define H_   1024
#define G3_  3072
#define BT_  65536

typedef unsigned long long ull;

// ===================== static device scratch =====================
__device__ float g_xpad [(size_t)BT_ * NP_];   // x zero-padded to 512 cols
__device__ float g_xproj[(size_t)BT_ * G3_];
__device__ float g_seq  [(size_t)BT_ * H_];
__device__ float g_h0   [B_ * H_];
__device__ float g_h1   [B_ * H_];
__device__ float g_z    [B_ * H_];
__device__ float g_za   [B_ * H_];
__device__ float g_scores[B_ * N_];
__device__ float g_wih0p[(size_t)G3_ * NP_];   // permuted + zero-padded
__device__ float g_whh0p[(size_t)G3_ * H_];
__device__ float g_wih1p[(size_t)G3_ * H_];
__device__ float g_whh1p[(size_t)G3_ * H_];
__device__ float g_bih0p[G3_];
__device__ float g_bhh0p[G3_];
__device__ float g_bih1p[G3_];
__device__ float g_bhh1p[G3_];

// ===================== helpers =====================
__device__ __forceinline__ ull pack2(float lo, float hi) {
    ull r; asm("mov.b64 %0, {%1, %2};" : "=l"(r) : "f"(lo), "f"(hi)); return r;
}
__device__ __forceinline__ float2 unpack2(ull v) {
    float2 r; asm("mov.b64 {%0, %1}, %2;" : "=f"(r.x), "=f"(r.y) : "l"(v)); return r;
}
__device__ __forceinline__ void ffma2(ull& d, ull a, ull b) {
    asm("fma.rn.f32x2 %0, %1, %2, %3;" : "=l"(d) : "l"(a), "l"(b), "l"(d));
}
__device__ __forceinline__ float sigf(float x) { return 1.f / (1.f + __expf(-x)); }

#define BM 128
#define BN 96
#define BK 16
#define NT 256

// ===================== guarded loaders (head only) =====================
__device__ __forceinline__ void load_tileA(const float* __restrict__ A, int M, int K,
                                           int m0, int k0, int am, int ak, float4* Apre)
{
    #pragma unroll
    for (int r = 0; r < 2; r++) {
        int gm = m0 + am + r * 64;
        int gk = k0 + ak;
        float4 v = make_float4(0.f, 0.f, 0.f, 0.f);
        if (gm < M) {
            if (gk + 3 < K) v = *(const float4*)(A + (size_t)gm * K + gk);
            else {
                if (gk + 0 < K) v.x = A[(size_t)gm * K + gk + 0];
                if (gk + 1 < K) v.y = A[(size_t)gm * K + gk + 1];
                if (gk + 2 < K) v.z = A[(size_t)gm * K + gk + 2];
                if (gk + 3 < K) v.w = A[(size_t)gm * K + gk + 3];
            }
        }
        Apre[r] = v;
    }
}
__device__ __forceinline__ void load_tileB(const float* __restrict__ Bm, int Nd, int K,
                                           int n0, int k0, int tid, float2* Bpre)
{
    #pragma unroll
    for (int j = 0; j < 3; j++) {
        int i2 = tid + j * 256;
        int bn = i2 >> 3;
        int bk = (i2 & 7) << 1;
        int gn = n0 + bn, gk = k0 + bk;
        float2 v = make_float2(0.f, 0.f);
        if (gn < Nd && gk < K) v = *(const float2*)(Bm + (size_t)gn * K + gk);
        Bpre[j] = v;
    }
}
// unguarded loaders (runtime row stride; all indices statically in-bounds)
__device__ __forceinline__ void load_tileA_u(const float* __restrict__ A, int strideE,
                                             int m0, int k0, int am, int ak, float4* Apre)
{
    #pragma unroll
    for (int r = 0; r < 2; r++)
        Apre[r] = *(const float4*)(A + (size_t)(m0 + am + r * 64) * strideE + k0 + ak);
}
__device__ __forceinline__ void load_tileB_u(const float* __restrict__ Bm, int strideE,
                                             int n0, int k0, int tid, float2* Bpre)
{
    #pragma unroll
    for (int j = 0; j < 3; j++) {
        int i2 = tid + j * 256;
        int bn = i2 >> 3;
        int bk = (i2 & 7) << 1;
        Bpre[j] = *(const float2*)(Bm + (size_t)(n0 + bn) * strideE + k0 + bk);
    }
}

// ===================== guarded GEMM (head only) =====================
__global__ __launch_bounds__(NT)
void gemm_f2(const float* __restrict__ A, const float* __restrict__ Bm,
             const float* __restrict__ bias, float* __restrict__ C,
             int M, int Nd, int K)
{
    __shared__ float As[BK][BM + 4];
    __shared__ float Bs[BK][BN + 2];
    const int tid = threadIdx.x;
    const int tx = tid & 15, ty = tid >> 4;
    const int m0 = blockIdx.y * BM, n0 = blockIdx.x * BN;
    const int am = tid >> 2;
    const int ak = (tid & 3) << 2;
    ull acc[4][6];
    #pragma unroll
    for (int i = 0; i < 4; i++)
        #pragma unroll
        for (int j = 0; j < 6; j++) acc[i][j] = 0ull;
    float4 Apre[2]; float2 Bpre[3];
    const int ntiles = (K + BK - 1) / BK;
    load_tileA(A, M, K, m0, 0, am, ak, Apre);
    load_tileB(Bm, Nd, K, n0, 0, tid, Bpre);
    for (int kt = 0; kt < ntiles; kt++) {
        #pragma unroll
        for (int r = 0; r < 2; r++) {
            As[ak + 0][am + r * 64] = Apre[r].x;
            As[ak + 1][am + r * 64] = Apre[r].y;
            As[ak + 2][am + r * 64] = Apre[r].z;
            As[ak + 3][am + r * 64] = Apre[r].w;
        }
        #pragma unroll
        for (int j = 0; j < 3; j++) {
            int i2 = tid + j * 256;
            int bn = i2 >> 3, bk = (i2 & 7) << 1;
            Bs[bk][bn]     = Bpre[j].x;
            Bs[bk + 1][bn] = Bpre[j].y;
        }
        __syncthreads();
        if (kt + 1 < ntiles) {
            load_tileA(A, M, K, m0, (kt + 1) * BK, am, ak, Apre);
            load_tileB(Bm, Nd, K, n0, (kt + 1) * BK, tid, Bpre);
        }
        #pragma unroll
        for (int k = 0; k < BK; k++) {
            ull av[4];
            #pragma unroll
            for (int i = 0; i < 4; i++) av[i] = *(const ull*)&As[k][ty * 8 + 2 * i];
            ull bv[6];
            #pragma unroll
            for (int j = 0; j < 6; j++) { float b = Bs[k][tx * 6 + j]; bv[j] = pack2(b, b); }
            #pragma unroll
            for (int i = 0; i < 4; i++)
                #pragma unroll
                for (int j = 0; j < 6; j++) ffma2(acc[i][j], av[i], bv[j]);
        }
        __syncthreads();
    }
    #pragma unroll
    for (int i = 0; i < 4; i++) {
        int gm0 = m0 + ty * 8 + 2 * i;
        #pragma unroll
        for (int j = 0; j < 6; j++) {
            int gn = n0 + tx * 6 + j;
            if (gn >= Nd) continue;
            float2 v = unpack2(acc[i][j]);
            float bb = bias ? bias[gn] : 0.f;
            if (gm0 < M)     C[(size_t)gm0 * Nd + gn]       = v.x + bb;
            if (gm0 + 1 < M) C[(size_t)(gm0 + 1) * Nd + gn] = v.y + bb;
        }
    }
}

// ===================== unguarded projection GEMM =====================
// M mult of 128, Nd mult of 96, K mult of 16. A stride=K, W stride=K, C stride=Nd.
__global__ __launch_bounds__(NT)
void gemm_f2u(const float* __restrict__ A, const float* __restrict__ Bm,
              const float* __restrict__ bias, float* __restrict__ C,
              int Nd, int K)
{
    __shared__ float As[BK][BM + 4];
    __shared__ float Bs[BK][BN + 2];
    const int tid = threadIdx.x;
    const int tx = tid & 15, ty = tid >> 4;
    const int m0 = blockIdx.y * BM, n0 = blockIdx.x * BN;
    const int am = tid >> 2;
    const int ak = (tid & 3) << 2;
    ull acc[4][6];
    #pragma unroll
    for (int i = 0; i < 4; i++)
        #pragma unroll
        for (int j = 0; j < 6; j++) acc[i][j] = 0ull;
    float4 Apre[2]; float2 Bpre[3];
    const int ntiles = K / BK;
    load_tileA_u(A, K, m0, 0, am, ak, Apre);
    load_tileB_u(Bm, K, n0, 0, tid, Bpre);
    for (int kt = 0; kt < ntiles; kt++) {
        #pragma unroll
        for (int r = 0; r < 2; r++) {
            As[ak + 0][am + r * 64] = Apre[r].x;
            As[ak + 1][am + r * 64] = Apre[r].y;
            As[ak + 2][am + r * 64] = Apre[r].z;
            As[ak + 3][am + r * 64] = Apre[r].w;
        }
        #pragma unroll
        for (int j = 0; j < 3; j++) {
            int i2 = tid + j * 256;
            int bn = i2 >> 3, bk = (i2 & 7) << 1;
            Bs[bk][bn]     = Bpre[j].x;
            Bs[bk + 1][bn] = Bpre[j].y;
        }
        __syncthreads();
        if (kt + 1 < ntiles) {
            load_tileA_u(A, K, m0, (kt + 1) * BK, am, ak, Apre);
            load_tileB_u(Bm, K, n0, (kt + 1) * BK, tid, Bpre);
        }
        #pragma unroll
        for (int k = 0; k < BK; k++) {
            ull av[4];
            #pragma unroll
            for (int i = 0; i < 4; i++) av[i] = *(const ull*)&As[k][ty * 8 + 2 * i];
            ull bv[6];
            #pragma unroll
            for (int j = 0; j < 6; j++) { float b = Bs[k][tx * 6 + j]; bv[j] = pack2(b, b); }
            #pragma unroll
            for (int i = 0; i < 4; i++)
                #pragma unroll
                for (int j = 0; j < 6; j++) ffma2(acc[i][j], av[i], bv[j]);
        }
        __syncthreads();
    }
    #pragma unroll
    for (int i = 0; i < 4; i++) {
        int gm0 = m0 + ty * 8 + 2 * i;
        #pragma unroll
        for (int j = 0; j < 6; j++) {
            int gn = n0 + tx * 6 + j;
            float2 v = unpack2(acc[i][j]);
            float bb = bias[gn];
            C[(size_t)gm0 * Nd + gn]       = v.x + bb;
            C[(size_t)(gm0 + 1) * Nd + gn] = v.y + bb;
        }
    }
}

// ===================== recurrence: unguarded (R14 champion) =====================
__global__ __launch_bounds__(NT)
void gru_step(const float* __restrict__ hin, const float* __restrict__ W,
              const float* __restrict__ bias, const float* __restrict__ xp,
              float* __restrict__ hout, float* __restrict__ seqp, int t)
{
    __shared__ float As[BK][BM + 4];
    __shared__ float Bs[BK][BN + 2];
    const int tid = threadIdx.x;
    const int tx = tid & 15, ty = tid >> 4;
    const int m0 = blockIdx.y * BM, n0 = blockIdx.x * BN;
    const int am = tid >> 2;
    const int ak = (tid & 3) << 2;
    ull acc[4][6];
    #pragma unroll
    for (int i = 0; i < 4; i++)
        #pragma unroll
        for (int j = 0; j < 6; j++) acc[i][j] = 0ull;
    float4 Apre[2]; float2 Bpre[3];
    const int ntiles = H_ / BK;       // 64
    load_tileA_u(hin, H_, m0, 0, am, ak, Apre);
    load_tileB_u(W, H_, n0, 0, tid, Bpre);
    for (int kt = 0; kt < ntiles; kt++) {
        #pragma unroll
        for (int r = 0; r < 2; r++) {
            As[ak + 0][am + r * 64] = Apre[r].x;
            As[ak + 1][am + r * 64] = Apre[r].y;
            As[ak + 2][am + r * 64] = Apre[r].z;
            As[ak + 3][am + r * 64] = Apre[r].w;
        }
        #pragma unroll
        for (int j = 0; j < 3; j++) {
            int i2 = tid + j * 256;
            int bn = i2 >> 3, bk = (i2 & 7) << 1;
            Bs[bk][bn]     = Bpre[j].x;
            Bs[bk + 1][bn] = Bpre[j].y;
        }
        __syncthreads();
        if (kt + 1 < ntiles) {
            load_tileA_u(hin, H_, m0, (kt + 1) * BK, am, ak, Apre);
            load_tileB_u(W, H_, n0, (kt + 1) * BK, tid, Bpre);
        }
        #pragma unroll
        for (int k = 0; k < BK; k++) {
            ull av[4];
            #pragma unroll
            for (int i = 0; i < 4; i++) av[i] = *(const ull*)&As[k][ty * 8 + 2 * i];
            ull bv[6];
            #pragma unroll
            for (int j = 0; j < 6; j++) { float b = Bs[k][tx * 6 + j]; bv[j] = pack2(b, b); }
            #pragma unroll
            for (int i = 0; i < 4; i++)
                #pragma unroll
                for (int j = 0; j < 6; j++) ffma2(acc[i][j], av[i], bv[j]);
        }
        __syncthreads();
    }

    const int col0 = n0 + tx * 6;      // two complete gate triples
    const int hu0  = col0 / 3;
    #pragma unroll
    for (int i = 0; i < 4; i++) {
        int b0 = m0 + ty * 8 + 2 * i;
        float ga[6], gb[6];
        #pragma unroll
        for (int j = 0; j < 6; j++) {
            float2 v = unpack2(acc[i][j]);
            ga[j] = v.x + bias[col0 + j];
            gb[j] = v.y + bias[col0 + j];
        }
        #pragma unroll
        for (int e = 0; e < 2; e++) {
            int b = b0 + e;
            const float* gg = e ? gb : ga;
            const float* xr = xp + ((size_t)b * T_ + t) * G3_ + col0;
            #pragma unroll
            for (int u = 0; u < 2; u++) {
                int c  = 3 * u;
                int hu = hu0 + u;
                float r  = sigf(xr[c + 0] + gg[c + 0]);
                float z  = sigf(xr[c + 1] + gg[c + 1]);
                float nn = tanhf(xr[c + 2] + r * gg[c + 2]);
                float hp = hin[(size_t)b * H_ + hu];
                float hv = (1.f - z) * nn + z * hp;
                hout[(size_t)b * H_ + hu] = hv;
                if (seqp) seqp[((size_t)b * T_ + t) * H_ + hu] = hv;
            }
        }
    }
}

// ===================== misc kernels =====================
// 1-D grid (BT_*NP_ elements) — gridDim.y limit bug fixed
__global__ void pad_x(const float* __restrict__ x, float* __restrict__ xpad)
{
    int idx = blockIdx.x * 256 + threadIdx.x;
    int row = idx >> 9;            // /512
    int k   = idx & (NP_ - 1);
    xpad[(size_t)row * NP_ + k] = (k < N_) ? x[(size_t)row * N_ + k] : 0.f;
}
__global__ void permute_w(const float* __restrict__ w, float* __restrict__ wp, int K)
{
    int c = blockIdx.y;
    int k = blockIdx.x * 256 + threadIdx.x;
    if (k >= K) return;
    int g = c % 3, h = c / 3;
    wp[(size_t)c * K + k] = w[(size_t)(g * H_ + h) * K + k];
}
// permute + pad to NP_ cols (src has N_ cols)
__global__ void permute_w_pad(const float* __restrict__ w, float* __restrict__ wp)
{
    int c = blockIdx.y;
    int k = blockIdx.x * 256 + threadIdx.x;
    if (k >= NP_) return;
    int g = c % 3, h = c / 3;
    wp[(size_t)c * NP_ + k] = (k < N_) ? w[(size_t)(g * H_ + h) * N_ + k] : 0.f;
}
__global__ void permute_b(const float* __restrict__ b, float* __restrict__ bp)
{
    int c = blockIdx.x * 256 + threadIdx.x;
    if (c < G3_) bp[c] = b[(c % 3) * H_ + c / 3];
}
__global__ void zero_kernel(float* __restrict__ p, int n)
{
    int i = blockIdx.x * blockDim.x + threadIdx.x;
    if (i < n) p[i] = 0.f;
}

__global__ __launch_bounds__(256)
void ln_silu(const float* __restrict__ z,
             const float* __restrict__ lng,
             const float* __restrict__ lnb,
             float* __restrict__ out)
{
    __shared__ float red[256];
    int b = blockIdx.x, tid = threadIdx.x;
    const float* row = z + (size_t)b * H_;
    float s = 0.f, s2 = 0.f;
    for (int i = tid; i < H_; i += 256) { float v = row[i]; s += v; s2 += v * v; }
    red[tid] = s; __syncthreads();
    for (int o = 128; o > 0; o >>= 1) { if (tid < o) red[tid] += red[tid + o]; __syncthreads(); }
    float mu = red[0] / H_;
    __syncthreads();
    red[tid] = s2; __syncthreads();
    for (int o = 128; o > 0; o >>= 1) { if (tid < o) red[tid] += red[tid + o]; __syncthreads(); }
    float var = red[0] / H_ - mu * mu;
    float inv = rsqrtf(var + 1e-5f);
    for (int i = tid; i < H_; i += 256) {
        float y = (row[i] - mu) * inv * lng[i] + lnb[i];
        out[(size_t)b * H_ + i] = y / (1.f + expf(-y));
    }
}

__global__ __launch_bounds__(512)
void softmax_rebalance(const float* __restrict__ scores,
                       float* __restrict__ out)
{
    __shared__ float red[512];
    int b = blockIdx.x, tid = threadIdx.x;
    float s = (tid < N_) ? scores[(size_t)b * N_ + tid] : -INFINITY;
    if (s < 0.f) s = -INFINITY;
    red[tid] = s; __syncthreads();
    for (int o = 256; o > 0; o >>= 1) { if (tid < o) red[tid] = fmaxf(red[tid], red[tid + o]); __syncthreads(); }
    float m = red[0]; __syncthreads();
    float e = (tid < N_) ? expf(s - m) : 0.f;
    red[tid] = e; __syncthreads();
    for (int o = 256; o > 0; o >>= 1) { if (tid < o) red[tid] += red[tid + o]; __syncthreads(); }
    float S = red[0]; __syncthreads();
    float w = e / S;
    w = fminf(fmaxf(w, 0.0f), 0.1f);
    for (int it = 0; it < 20; it++) {
        red[tid] = (tid < N_) ? w : 0.f; __syncthreads();
        for (int o = 256; o > 0; o >>= 1) { if (tid < o) red[tid] += red[tid + o]; __syncthreads(); }
        float tot = red[0]; __syncthreads();
        float excess = tot - 1.0f;
        bool  active = excess > 1e-6f;
        float sur = fmaxf(w - 0.1f, 0.f);
        red[tid] = (tid < N_) ? sur : 0.f; __syncthreads();
        for (int o = 256; o > 0; o >>= 1) { if (tid < o) red[tid] += red[tid + o]; __syncthreads(); }
        float totsur = red[0]; __syncthreads();
        float upd = (totsur > 0.f)
                  ? w - sur / fmaxf(totsur, 1e-12f) * excess
                  : w - excess / (float)N_;
        upd = fminf(fmaxf(upd, 0.0f), 0.1f);
        if (active) w = upd;
    }
    if (tid < N_) out[(size_t)b * N_ + tid] = w;
}

// ===================== orchestration =====================
extern "C" void kernel_launch(void* const* d_in, const int* in_sizes, int n_in,
                              void* d_out, int out_size)
{
    const float* x     = (const float*)d_in[0];
    const float* w_ih0 = (const float*)d_in[1];
    const float* w_hh0 = (const float*)d_in[2];
    const float* b_ih0 = (const float*)d_in[3];
    const float* b_hh0 = (const float*)d_in[4];
    const float* w_ih1 = (const float*)d_in[5];
    const float* w_hh1 = (const float*)d_in[6];
    const float* b_ih1 = (const float*)d_in[7];
    const float* b_hh1 = (const float*)d_in[8];
    const float* w1    = (const float*)d_in[9];
    const float* b1    = (const float*)d_in[10];
    const float* ln_g  = (const float*)d_in[11];
    const float* ln_b  = (const float*)d_in[12];
    const float* w2    = (const float*)d_in[13];
    const float* b2    = (const float*)d_in[14];
    float* out = (float*)d_out;

    void* p;
    float *xpad, *xproj, *seq, *h0, *h1, *z, *za, *scores;
    float *wih0p, *whh0p, *wih1p, *whh1p, *bih0p, *bhh0p, *bih1p, *bhh1p;
    cudaGetSymbolAddress(&p, g_xpad);   xpad   = (float*)p;
    cudaGetSymbolAddress(&p, g_xproj);  xproj  = (float*)p;
    cudaGetSymbolAddress(&p, g_seq);    seq    = (float*)p;
    cudaGetSymbolAddress(&p, g_h0);     h0     = (float*)p;
    cudaGetSymbolAddress(&p, g_h1);     h1     = (float*)p;
    cudaGetSymbolAddress(&p, g_z);      z      = (float*)p;
    cudaGetSymbolAddress(&p, g_za);     za     = (float*)p;
    cudaGetSymbolAddress(&p, g_scores); scores = (float*)p;
    cudaGetSymbolAddress(&p, g_wih0p);  wih0p  = (float*)p;
    cudaGetSymbolAddress(&p, g_whh0p);  whh0p  = (float*)p;
    cudaGetSymbolAddress(&p, g_wih1p);  wih1p  = (float*)p;
    cudaGetSymbolAddress(&p, g_whh1p);  whh1p  = (float*)p;
    cudaGetSymbolAddress(&p, g_bih0p);  bih0p  = (float*)p;
    cudaGetSymbolAddress(&p, g_bhh0p);  bhh0p  = (float*)p;
    cudaGetSymbolAddress(&p, g_bih1p);  bih1p  = (float*)p;
    cudaGetSymbolAddress(&p, g_bhh1p);  bhh1p  = (float*)p;

    // preprocessing: pad x, permute/pad weights, permute biases
    pad_x<<<(BT_ * NP_) / 256, 256>>>(x, xpad);
    permute_w_pad<<<dim3(NP_ / 256, G3_), 256>>>(w_ih0, wih0p);
    permute_w<<<dim3((H_ + 255) / 256, G3_), 256>>>(w_hh0, whh0p, H_);
    permute_w<<<dim3((H_ + 255) / 256, G3_), 256>>>(w_ih1, wih1p, H_);
    permute_w<<<dim3((H_ + 255) / 256, G3_), 256>>>(w_hh1, whh1p, H_);
    permute_b<<<(G3_ + 255) / 256, 256>>>(b_ih0, bih0p);
    permute_b<<<(G3_ + 255) / 256, 256>>>(b_hh0, bhh0p);
    permute_b<<<(G3_ + 255) / 256, 256>>>(b_ih1, bih1p);
    permute_b<<<(G3_ + 255) / 256, 256>>>(b_hh1, bhh1p);

    // layer 0 input projection (unguarded, K=512 padded)
    gemm_f2u<<<dim3(G3_ / BN, BT_ / BM), NT>>>(xpad, wih0p, bih0p, xproj, G3_, NP_);
    zero_kernel<<<(B_ * H_ + 255) / 256, 256>>>(h0, B_ * H_);

    // layer 0 recurrence
    for (int t = 0; t < T_; t++) {
        float* hin  = (t & 1) ? h1 : h0;
        float* hout = (t & 1) ? h0 : h1;
        gru_step<<<dim3(G3_ / BN, B_ / BM), NT>>>(hin, whh0p, bhh0p, xproj, hout, seq, t);
    }

    // layer 1 input projection (unguarded, K=1024)
    gemm_f2u<<<dim3(G3_ / BN, BT_ / BM), NT>>>(seq, wih1p, bih1p, xproj, G3_, H_);
    zero_kernel<<<(B_ * H_ + 255) / 256, 256>>>(h0, B_ * H_);

    // layer 1 recurrence
    for (int t = 0; t < T_; t++) {
        float* hin  = (t & 1) ? h1 : h0;
        float* hout = (t & 1) ? h0 : h1;
        gru_step<<<dim3(G3_ / BN, B_ / BM), NT>>>(hin, whh1p, bhh1p, xproj, hout, nullptr, t);
    }

    // head (guarded; small)
    gemm_f2<<<dim3((H_ + BN - 1) / BN, B_ / BM), NT>>>(h0, w1, b1, z, B_, H_, H_);
    ln_silu<<<B_, 256>>>(z, ln_g, ln_b, za);
    gemm_f2<<<dim3((N_ + BN - 1) / BN, B_ / BM), NT>>>(za, w2, b2, scores, B_, N_, H_);
    softmax_rebalance<<<B_, 512>>>(scores, out);
}